// round 14
// baseline (speedup 1.0000x reference)
#include <cuda_runtime.h>
#include <cuda_fp16.h>
#include <cstdint>
#include <math.h>

#define B_      4096
#define S_      32
#define E_      128
#define H_      512
#define V_TGT_  128
#define NCOL_   2048          // 4*H, gate-interleaved col' = h*4 + gate
#define KC_     640           // E + H
#define SOS_    1
#define NSTEP_  64
#define BH_     (B_ * H_)
#define XSTEP_  (B_ * E_)

// LSTM step: 2 sequential 128x128 n-tiles per CTA, 128 thr (4 warps),
// warp tile 64x64, BK=64 double buffer, 2 CTAs/SM.
#define BM_     128
#define BN_     128
#define NKT_    10            // 640 / 64
#define STAGE_  32768         // A 16K | W 16K
#define OFF_W_  16384
#define CBUF_   65536         // half-C buffer: 64 x 132 fp32 = 33792 B
#define SMEM_LSTM_ 101376     // 1K align + 64K stages + 33.8K C
#define SMEM_LG_   69632      // logits: 1K align + 64K stages (C overlaps)

// ---------------------------------------------------------------------------
// Device scratch (static; no allocations allowed)
// ---------------------------------------------------------------------------
__device__ __align__(256) __half g_Xf[NSTEP_ * XSTEP_];      // emb slice, all steps
__device__ __align__(256) __half g_Wf[2][NCOL_ * KC_];       // [dir][n'][k]
__device__ __align__(256) float  g_bias[2][NCOL_];
__device__ __align__(256) __half g_hf[2][BH_];               // ping-pong hidden
__device__ __align__(256) float  g_c[BH_];
__device__ __align__(256) __half g_hsf[S_ * BH_];            // decoder hiddens
__device__ __align__(256) __half g_WoVf[V_TGT_ * H_];        // [v][k]

// ---------------------------------------------------------------------------
__device__ __forceinline__ uint32_t smem_u32(const void* p) {
    uint32_t a;
    asm("{ .reg .u64 t; cvta.to.shared.u64 t, %1; cvt.u32.u64 %0, t; }" : "=r"(a) : "l"(p));
    return a;
}
__device__ __forceinline__ void cp16(uint32_t dst, const void* src) {
    asm volatile("cp.async.cg.shared.global [%0], [%1], 16;" :: "r"(dst), "l"(src));
}
__device__ __forceinline__ void ldm_x4(uint32_t* r, uint32_t addr) {
    asm volatile("ldmatrix.sync.aligned.m8n8.x4.shared.b16 {%0,%1,%2,%3}, [%4];"
        : "=r"(r[0]), "=r"(r[1]), "=r"(r[2]), "=r"(r[3]) : "r"(addr));
}
__device__ __forceinline__ void mma16816(float* c, const uint32_t* a, uint32_t b0, uint32_t b1) {
    asm volatile("mma.sync.aligned.m16n8k16.row.col.f32.f16.f16.f32 "
        "{%0,%1,%2,%3}, {%4,%5,%6,%7}, {%8,%9}, {%0,%1,%2,%3};"
        : "+f"(c[0]), "+f"(c[1]), "+f"(c[2]), "+f"(c[3])
        : "r"(a[0]), "r"(a[1]), "r"(a[2]), "r"(a[3]), "r"(b0), "r"(b1));
}
__device__ __forceinline__ float fsig(float x)  { return __fdividef(1.0f, 1.0f + __expf(-x)); }
__device__ __forceinline__ float ftanh(float x) { return 1.0f - __fdividef(2.0f, __expf(2.0f * x) + 1.0f); }

// ---------------------------------------------------------------------------
// Prep: fp16 weights (gate-interleaved [n'][k]), fp16 embedding slices for all
// 64 steps, summed biases, fp16 WoutT, zeroed state.
// ---------------------------------------------------------------------------
__global__ void prep_kernel(const int* __restrict__ src_seq, const int* __restrict__ tgt_seq,
                            const float* __restrict__ emb_src, const float* __restrict__ emb_tgt,
                            const float* __restrict__ eWih, const float* __restrict__ eWhh,
                            const float* __restrict__ eBih, const float* __restrict__ eBhh,
                            const float* __restrict__ dWih, const float* __restrict__ dWhh,
                            const float* __restrict__ dBih, const float* __restrict__ dBhh,
                            const float* __restrict__ Wout)
{
    const long long t0 = (long long)blockIdx.x * blockDim.x + threadIdx.x;
    const long long st = (long long)gridDim.x * blockDim.x;

    for (long long i = t0; i < (long long)NSTEP_ * XSTEP_; i += st) {
        int k = (int)(i & 127);
        long long sm = i >> 7;
        int m = (int)(sm & (B_ - 1));
        int s = (int)(sm >> 12);
        int tok; const float* emb;
        if (s < 32)       { tok = src_seq[m * S_ + s]; emb = emb_src; }
        else if (s == 32) { tok = SOS_;                emb = emb_tgt; }
        else              { tok = tgt_seq[m * S_ + (s - 33)]; emb = emb_tgt; }
        g_Xf[i] = __float2half_rn(emb[tok * E_ + k]);
    }
    for (long long i = t0; i < (long long)NCOL_ * KC_; i += st) {
        int np = (int)(i / KC_);
        int k  = (int)(i - (long long)np * KC_);
        int g = np & 3, n = np >> 2;
        int r = g * H_ + n;                       // PyTorch [i,f,g,o] gate layout
        float ve = (k < E_) ? eWih[r * E_ + k] : eWhh[r * H_ + (k - E_)];
        float vd = (k < E_) ? dWih[r * E_ + k] : dWhh[r * H_ + (k - E_)];
        g_Wf[0][i] = __float2half_rn(ve);
        g_Wf[1][i] = __float2half_rn(vd);
    }
    for (long long i = t0; i < NCOL_; i += st) {
        int g = (int)i & 3, n = (int)i >> 2;
        int r = g * H_ + n;
        g_bias[0][i] = eBih[r] + eBhh[r];
        g_bias[1][i] = dBih[r] + dBhh[r];
    }
    for (long long i = t0; i < (long long)V_TGT_ * H_; i += st)
        g_WoVf[i] = __float2half_rn(Wout[i]);    // Wout is [V][H] = [n][k]
    __half z = __float2half_rn(0.0f);
    for (long long i = t0; i < BH_; i += st) {
        g_hf[0][i] = z;
        g_c[i] = 0.0f;
    }
}

// ---------------------------------------------------------------------------
// Stage loader (128 threads): kt in [0,10), buffer = kt & 1.
// ---------------------------------------------------------------------------
__device__ __forceinline__ void load_tile(uint32_t base, int kt, int m0, int n0p, int tid,
    const __half* __restrict__ Xf, const __half* __restrict__ Hf,
    const __half* __restrict__ Wf)
{
    const int kofs = kt * 64;
    uint32_t sb = base + (uint32_t)(kt & 1) * STAGE_;
    #pragma unroll
    for (int i = 0; i < 8; i++) {                 // A: 128 rows x 8 chunks(16B)
        int idx = tid + i * 128;
        int row = idx >> 3, c = idx & 7;
        uint32_t doff = (uint32_t)(row * 128 + ((c * 16) ^ ((row & 7) << 4)));
        const __half* src = (kt < 2)
            ? Xf + (size_t)(m0 + row) * E_ + kofs + c * 8
            : Hf + (size_t)(m0 + row) * H_ + (kofs - E_) + c * 8;
        cp16(sb + doff, src);
    }
    #pragma unroll
    for (int i = 0; i < 8; i++) {                 // W: 128 rows x 8 chunks
        int idx = tid + i * 128;
        int row = idx >> 3, c = idx & 7;
        uint32_t doff = (uint32_t)(row * 128 + ((c * 16) ^ ((row & 7) << 4)));
        cp16(sb + OFF_W_ + doff, Wf + (size_t)(n0p + row) * KC_ + kofs + c * 8);
    }
    asm volatile("cp.async.commit_group;" ::: "memory");
}

// ---------------------------------------------------------------------------
// Fused LSTM step: fp16 mma, fp32 accum; 4 warps, warp tile 64x64,
// fragment double-buffered; 2 n-tiles per CTA (one wave).
// ---------------------------------------------------------------------------
__global__ __launch_bounds__(128, 2)
void lstm_step(int ss, int dir, int par, const int* __restrict__ src_len)
{
    extern __shared__ char dyn_smem[];
    __shared__ __align__(16) float bias_s[256];

    const int tid  = threadIdx.x;
    const int lane = tid & 31;
    const int wid  = tid >> 5;           // 0..3
    const int warp_m = wid & 1;          // 64-row half
    const int warp_n = wid >> 1;         // 0..1 -> 64-col half
    const int m0    = blockIdx.x * BM_;
    const int nbase = blockIdx.y * 256;  // two 128-col tiles

    uint32_t base = (smem_u32(dyn_smem) + 1023u) & ~1023u;
    float* Cs;
    {
        uintptr_t g = (uintptr_t)dyn_smem;
        uintptr_t delta = (uintptr_t)(base - smem_u32(dyn_smem));
        Cs = (float*)(g + delta + CBUF_);
    }

    const __half* Xf   = g_Xf + (size_t)ss * XSTEP_;
    const __half* Wf   = g_Wf[dir];
    const __half* hf_s = g_hf[par];
    __half*       hf_d = g_hf[par ^ 1];

    #pragma unroll
    for (int i = tid; i < 256; i += 128) bias_s[i] = g_bias[dir][nbase + i];

    // ldmatrix address bases
    uint32_t aRow[4], aXor[4];
    #pragma unroll
    for (int mt = 0; mt < 4; mt++) {
        int row = warp_m * 64 + mt * 16 + (lane & 15);
        aRow[mt] = (uint32_t)(row * 128 + ((lane >> 4) * 16));
        aXor[mt] = (uint32_t)((row & 7) << 4);
    }
    uint32_t bRow[4], bXor[4];
    #pragma unroll
    for (int bt = 0; bt < 4; bt++) {
        int row = warp_n * 64 + bt * 16 + ((lane >> 4) & 1) * 8 + (lane & 7);
        bRow[bt] = (uint32_t)(row * 128 + (((lane >> 3) & 1) * 16));
        bXor[bt] = (uint32_t)((row & 7) << 4);
    }

    // prologue for tile 0
    load_tile(base, 0, m0, nbase, tid, Xf, hf_s, Wf);
    load_tile(base, 1, m0, nbase, tid, Xf, hf_s, Wf);

    for (int t = 0; t < 2; t++) {
        const int n0p = nbase + t * BN_;
        const int hq0 = n0p >> 2;

        float acc[4][8][4];
        #pragma unroll
        for (int mt = 0; mt < 4; mt++)
            #pragma unroll
            for (int nt = 0; nt < 8; nt++)
                #pragma unroll
                for (int q = 0; q < 4; q++) acc[mt][nt][q] = 0.0f;

        for (int s = 0; s < NKT_; s++) {
            if (s < NKT_ - 1) asm volatile("cp.async.wait_group 1;" ::: "memory");
            else              asm volatile("cp.async.wait_group 0;" ::: "memory");
            __syncthreads();

            const uint32_t Ab = base + (uint32_t)(s & 1) * STAGE_;
            const uint32_t Wb = Ab + OFF_W_;

            uint32_t a[2][4][4], w[2][4][4];
            // prefetch k16 = 0
            #pragma unroll
            for (int mt = 0; mt < 4; mt++)
                ldm_x4(a[0][mt], Ab + (aRow[mt] ^ aXor[mt]));
            #pragma unroll
            for (int bt = 0; bt < 4; bt++)
                ldm_x4(w[0][bt], Wb + (bRow[bt] ^ bXor[bt]));

            #pragma unroll
            for (int k16 = 0; k16 < 4; k16++) {
                const int cur = k16 & 1, nxt = cur ^ 1;
                if (k16 < 3) {
                    uint32_t kb = (uint32_t)((k16 + 1) * 32);
                    #pragma unroll
                    for (int mt = 0; mt < 4; mt++)
                        ldm_x4(a[nxt][mt], Ab + ((aRow[mt] + kb) ^ aXor[mt]));
                    #pragma unroll
                    for (int bt = 0; bt < 4; bt++)
                        ldm_x4(w[nxt][bt], Wb + ((bRow[bt] + kb) ^ bXor[bt]));
                }
                #pragma unroll
                for (int mt = 0; mt < 4; mt++)
                    #pragma unroll
                    for (int nt = 0; nt < 8; nt++) {
                        int bt = nt >> 1, q = nt & 1;
                        mma16816(acc[mt][nt], a[cur][mt], w[cur][bt][2 * q], w[cur][bt][2 * q + 1]);
                    }
            }
            __syncthreads();
            if (s + 2 < NKT_)
                load_tile(base, s + 2, m0, n0p, tid, Xf, hf_s, Wf);
        }

        // prefetch tile 1's first two stages (overlaps with tile-0 epilogue)
        if (t == 0) {
            load_tile(base, 0, m0, nbase + BN_, tid, Xf, hf_s, Wf);
            load_tile(base, 1, m0, nbase + BN_, tid, Xf, hf_s, Wf);
        }

        // -------- epilogue in two 64-row halves (C buffer is separate) --------
        #pragma unroll
        for (int half = 0; half < 2; half++) {
            if (warp_m == half) {
                #pragma unroll
                for (int mt = 0; mt < 4; mt++)
                    #pragma unroll
                    for (int nt = 0; nt < 8; nt++) {
                        int r   = mt * 16 + (lane >> 2);        // local 0..63
                        int col = warp_n * 64 + nt * 8 + 2 * (lane & 3);
                        Cs[r * 132 + col]           = acc[mt][nt][0];
                        Cs[r * 132 + col + 1]       = acc[mt][nt][1];
                        Cs[(r + 8) * 132 + col]     = acc[mt][nt][2];
                        Cs[(r + 8) * 132 + col + 1] = acc[mt][nt][3];
                    }
            }
            __syncthreads();

            // 64 rows x 32 h-units = 2048 cells, 16 per thread
            #pragma unroll
            for (int i = 0; i < 16; i++) {
                int cell = i * 128 + tid;
                int m_ll = cell >> 5;
                int h_l  = cell & 31;
                int m = m0 + half * 64 + m_ll;
                size_t idx = (size_t)m * H_ + hq0 + h_l;
                bool frozen = (src_len != nullptr) && (ss >= src_len[m]);
                if (frozen) {
                    hf_d[idx] = hf_s[idx];
                } else {
                    const float* gp = &Cs[m_ll * 132 + h_l * 4];
                    float gi = gp[0] + bias_s[t * 128 + h_l * 4 + 0];
                    float gf = gp[1] + bias_s[t * 128 + h_l * 4 + 1];
                    float gg = gp[2] + bias_s[t * 128 + h_l * 4 + 2];
                    float go = gp[3] + bias_s[t * 128 + h_l * 4 + 3];
                    float cc = fsig(gf) * g_c[idx] + fsig(gi) * ftanh(gg);
                    float hv = fsig(go) * ftanh(cc);
                    g_c[idx] = cc;
                    __half hh = __float2half_rn(hv);
                    hf_d[idx] = hh;
                    if (dir) g_hsf[(size_t)(ss - 32) * BH_ + idx] = hh;
                }
            }
            __syncthreads();
        }
    }
}

// ---------------------------------------------------------------------------
// Logits: (131072, 512) @ (512, 128) + b_out; 4 m-tiles per CTA (one wave).
// (unchanged from R13: 256 thr, warp tile 64x32)
// ---------------------------------------------------------------------------
#define LNKT_ 8   // 512 / 64

__device__ __forceinline__ void load_tile_lg(uint32_t base, int kt, int m0, int tid)
{
    const int kofs = kt * 64;
    uint32_t sb = base + (uint32_t)(kt & 1) * STAGE_;
    #pragma unroll
    for (int i = 0; i < 4; i++) {
        int idx = tid + i * 256;
        int row = idx >> 3, c = idx & 7;
        uint32_t doff = (uint32_t)(row * 128 + ((c * 16) ^ ((row & 7) << 4)));
        cp16(sb + doff, g_hsf + (size_t)(m0 + row) * H_ + kofs + c * 8);
    }
    #pragma unroll
    for (int i = 0; i < 4; i++) {
        int idx = tid + i * 256;
        int row = idx >> 3, c = idx & 7;
        uint32_t doff = (uint32_t)(row * 128 + ((c * 16) ^ ((row & 7) << 4)));
        cp16(sb + OFF_W_ + doff, g_WoVf + (size_t)row * H_ + kofs + c * 8);
    }
    asm volatile("cp.async.commit_group;" ::: "memory");
}

__global__ __launch_bounds__(256, 2)
void logits_kernel(const float* __restrict__ b_out, float* __restrict__ out)
{
    extern __shared__ char dyn_smem[];

    const int tid  = threadIdx.x;
    const int lane = tid & 31;
    const int wid  = tid >> 5;
    const int warp_m = wid & 1;
    const int warp_n = wid >> 1;

    uint32_t base = (smem_u32(dyn_smem) + 1023u) & ~1023u;
    float* Cs;
    {
        uintptr_t g = (uintptr_t)dyn_smem;
        uintptr_t delta = (uintptr_t)(base - smem_u32(dyn_smem));
        Cs = (float*)(g + delta);
    }

    uint32_t aRow[4], aXor[4];
    #pragma unroll
    for (int mt = 0; mt < 4; mt++) {
        int row = warp_m * 64 + mt * 16 + (lane & 15);
        aRow[mt] = (uint32_t)(row * 128 + ((lane >> 4) * 16));
        aXor[mt] = (uint32_t)((row & 7) << 4);
    }
    uint32_t bRow[2], bXor[2];
    #pragma unroll
    for (int bt = 0; bt < 2; bt++) {
        int row = warp_n * 32 + bt * 16 + ((lane >> 4) & 1) * 8 + (lane & 7);
        bRow[bt] = (uint32_t)(row * 128 + (((lane >> 3) & 1) * 16));
        bXor[bt] = (uint32_t)((row & 7) << 4);
    }

    for (int tt2 = 0; tt2 < 4; tt2++) {
        const int m0 = (blockIdx.x * 4 + tt2) * 128;

        float acc[4][4][4];
        #pragma unroll
        for (int mt = 0; mt < 4; mt++)
            #pragma unroll
            for (int nt = 0; nt < 4; nt++)
                #pragma unroll
                for (int q = 0; q < 4; q++) acc[mt][nt][q] = 0.0f;

        load_tile_lg(base, 0, m0, tid);
        load_tile_lg(base, 1, m0, tid);

        for (int s = 0; s < LNKT_; s++) {
            if (s < LNKT_ - 1) asm volatile("cp.async.wait_group 1;" ::: "memory");
            else               asm volatile("cp.async.wait_group 0;" ::: "memory");
            __syncthreads();

            const uint32_t Ab = base + (uint32_t)(s & 1) * STAGE_;
            const uint32_t Wb = Ab + OFF_W_;

            #pragma unroll
            for (int k16 = 0; k16 < 4; k16++) {
                uint32_t kb = (uint32_t)(k16 * 32);
                uint32_t a[4][4], w[2][4];
                #pragma unroll
                for (int mt = 0; mt < 4; mt++)
                    ldm_x4(a[mt], Ab + ((aRow[mt] + kb) ^ aXor[mt]));
                #pragma unroll
                for (int bt = 0; bt < 2; bt++)
                    ldm_x4(w[bt], Wb + ((bRow[bt] + kb) ^ bXor[bt]));
                #pragma unroll
                for (int mt = 0; mt < 4; mt++)
                    #pragma unroll
                    for (int nt = 0; nt < 4; nt++) {
                        int bt = nt >> 1, q = nt & 1;
                        mma16816(acc[mt][nt], a[mt], w[bt][2 * q], w[bt][2 * q + 1]);
                    }
            }
            __syncthreads();
            if (s + 2 < LNKT_) load_tile_lg(base, s + 2, m0, tid);
        }

        // epilogue: C -> smem (reuses stage bufs; drained) -> out
        #pragma unroll
        for (int mt = 0; mt < 4; mt++)
            #pragma unroll
            for (int nt = 0; nt < 4; nt++) {
                int r   = warp_m * 64 + mt * 16 + (lane >> 2);
                int col = warp_n * 32 + nt * 8 + 2 * (lane & 3);
                Cs[r * 132 + col]           = acc[mt][nt][0];
                Cs[r * 132 + col + 1]       = acc[mt][nt][1];
                Cs[(r + 8) * 132 + col]     = acc[mt][nt][2];
                Cs[(r + 8) * 132 + col + 1] = acc[mt][nt][3];
            }
        __syncthreads();

        #pragma unroll
        for (int i = 0; i < 64; i++) {
            int cell = i * 256 + tid;
            int r = cell >> 7;
            int v = cell & 127;
            int m_g = m0 + r;                 // m_g = t*4096 + b
            int b  = m_g & (B_ - 1);
            int tt = m_g >> 12;
            out[((size_t)b * S_ + tt) * V_TGT_ + v] = Cs[r * 132 + v] + b_out[v];
        }
        __syncthreads();   // before next tile's loads overwrite C region
    }
}

// ---------------------------------------------------------------------------
extern "C" void kernel_launch(void* const* d_in, const int* in_sizes, int n_in,
                              void* d_out, int out_size)
{
    (void)in_sizes; (void)n_in; (void)out_size;
    const int*   src_seq = (const int*)  d_in[0];
    const int*   src_len = (const int*)  d_in[1];
    const int*   tgt_seq = (const int*)  d_in[2];
    const float* emb_src = (const float*)d_in[3];
    const float* eWih    = (const float*)d_in[4];
    const float* eWhh    = (const float*)d_in[5];
    const float* eBih    = (const float*)d_in[6];
    const float* eBhh    = (const float*)d_in[7];
    const float* emb_tgt = (const float*)d_in[8];
    const float* dWih    = (const float*)d_in[9];
    const float* dWhh    = (const float*)d_in[10];
    const float* dBih    = (const float*)d_in[11];
    const float* dBhh    = (const float*)d_in[12];
    const float* Wout    = (const float*)d_in[13];
    const float* bout    = (const float*)d_in[14];
    float*       out     = (float*)d_out;

    cudaFuncSetAttribute(lstm_step, cudaFuncAttributeMaxDynamicSharedMemorySize, SMEM_LSTM_);
    cudaFuncSetAttribute(logits_kernel, cudaFuncAttributeMaxDynamicSharedMemorySize, SMEM_LG_);

    prep_kernel<<<4096, 256>>>(src_seq, tgt_seq, emb_src, emb_tgt,
                               eWih, eWhh, eBih, eBhh,
                               dWih, dWhh, dBih, dBhh, Wout);

    dim3 grid(B_ / BM_, NCOL_ / 256);   // (32, 8) = 256 CTAs, one wave
    for (int s = 0; s < 32; s++)
        lstm_step<<<grid, 128, SMEM_LSTM_>>>(s, 0, s & 1, src_len);
    for (int s = 32; s < 64; s++)
        lstm_step<<<grid, 128, SMEM_LSTM_>>>(s, 1, s & 1, nullptr);

    logits_kernel<<<(B_ * S_) / 128 / 4, 256, SMEM_LG_>>>(bout, out);
}

// round 15
// speedup vs baseline: 1.1005x; 1.1005x over previous
#include <cuda_runtime.h>
#include <cuda_fp16.h>
#include <cstdint>
#include <math.h>

#define B_      4096
#define S_      32
#define E_      128
#define H_      512
#define V_TGT_  128
#define NCOL_   2048          // 4*H, gate-interleaved col' = h*4 + gate
#define KC_     640           // E + H
#define SOS_    1
#define NSTEP_  64
#define BH_     (B_ * H_)
#define XSTEP_  (B_ * E_)

// LSTM step: 128x128 tile, 256 thr (8 warps, warp tile 64x32), BK=64,
// THREE-stage cp.async pipeline, 2 CTAs/SM.
#define BM_     128
#define BN_     128
#define NKT_    10            // 640 / 64
#define STAGE_  32768         // A 16K | W 16K
#define OFF_W_  16384
#define SMEM_DYN_ 99328       // 1K align + 3*32K stages (C 128x132 overlays)

// ---------------------------------------------------------------------------
// Device scratch (static; no allocations allowed)
// ---------------------------------------------------------------------------
__device__ __align__(256) __half g_Xf[NSTEP_ * XSTEP_];      // emb slice, all steps
__device__ __align__(256) __half g_Wf[2][NCOL_ * KC_];       // [dir][n'][k]
__device__ __align__(256) float  g_bias[2][NCOL_];
__device__ __align__(256) __half g_hf[2][BH_];               // ping-pong hidden
__device__ __align__(256) float  g_c[BH_];
__device__ __align__(256) __half g_hsf[S_ * BH_];            // decoder hiddens
__device__ __align__(256) __half g_WoVf[V_TGT_ * H_];        // [v][k]

// ---------------------------------------------------------------------------
__device__ __forceinline__ uint32_t smem_u32(const void* p) {
    uint32_t a;
    asm("{ .reg .u64 t; cvta.to.shared.u64 t, %1; cvt.u32.u64 %0, t; }" : "=r"(a) : "l"(p));
    return a;
}
__device__ __forceinline__ void cp16(uint32_t dst, const void* src) {
    asm volatile("cp.async.cg.shared.global [%0], [%1], 16;" :: "r"(dst), "l"(src));
}
__device__ __forceinline__ void ldm_x4(uint32_t* r, uint32_t addr) {
    asm volatile("ldmatrix.sync.aligned.m8n8.x4.shared.b16 {%0,%1,%2,%3}, [%4];"
        : "=r"(r[0]), "=r"(r[1]), "=r"(r[2]), "=r"(r[3]) : "r"(addr));
}
__device__ __forceinline__ void mma16816(float* c, const uint32_t* a, uint32_t b0, uint32_t b1) {
    asm volatile("mma.sync.aligned.m16n8k16.row.col.f32.f16.f16.f32 "
        "{%0,%1,%2,%3}, {%4,%5,%6,%7}, {%8,%9}, {%0,%1,%2,%3};"
        : "+f"(c[0]), "+f"(c[1]), "+f"(c[2]), "+f"(c[3])
        : "r"(a[0]), "r"(a[1]), "r"(a[2]), "r"(a[3]), "r"(b0), "r"(b1));
}
__device__ __forceinline__ float fsig(float x)  { return __fdividef(1.0f, 1.0f + __expf(-x)); }
__device__ __forceinline__ float ftanh(float x) { return 1.0f - __fdividef(2.0f, __expf(2.0f * x) + 1.0f); }

// steady-state wait for 3-deep pipeline: stage s is complete when at most
// min(2, NITER-1-s) groups remain pending.
#define PIPE_WAIT(s, NITER) do { \
    if ((s) < (NITER) - 2)       asm volatile("cp.async.wait_group 2;" ::: "memory"); \
    else if ((s) == (NITER) - 2) asm volatile("cp.async.wait_group 1;" ::: "memory"); \
    else                         asm volatile("cp.async.wait_group 0;" ::: "memory"); \
} while (0)

// ---------------------------------------------------------------------------
// Prep: fp16 weights (gate-interleaved [n'][k]), fp16 embedding slices for all
// 64 steps, summed biases, fp16 WoutT, zeroed state.
// ---------------------------------------------------------------------------
__global__ void prep_kernel(const int* __restrict__ src_seq, const int* __restrict__ tgt_seq,
                            const float* __restrict__ emb_src, const float* __restrict__ emb_tgt,
                            const float* __restrict__ eWih, const float* __restrict__ eWhh,
                            const float* __restrict__ eBih, const float* __restrict__ eBhh,
                            const float* __restrict__ dWih, const float* __restrict__ dWhh,
                            const float* __restrict__ dBih, const float* __restrict__ dBhh,
                            const float* __restrict__ Wout)
{
    const long long t0 = (long long)blockIdx.x * blockDim.x + threadIdx.x;
    const long long st = (long long)gridDim.x * blockDim.x;

    for (long long i = t0; i < (long long)NSTEP_ * XSTEP_; i += st) {
        int k = (int)(i & 127);
        long long sm = i >> 7;
        int m = (int)(sm & (B_ - 1));
        int s = (int)(sm >> 12);
        int tok; const float* emb;
        if (s < 32)       { tok = src_seq[m * S_ + s]; emb = emb_src; }
        else if (s == 32) { tok = SOS_;                emb = emb_tgt; }
        else              { tok = tgt_seq[m * S_ + (s - 33)]; emb = emb_tgt; }
        g_Xf[i] = __float2half_rn(emb[tok * E_ + k]);
    }
    for (long long i = t0; i < (long long)NCOL_ * KC_; i += st) {
        int np = (int)(i / KC_);
        int k  = (int)(i - (long long)np * KC_);
        int g = np & 3, n = np >> 2;
        int r = g * H_ + n;                       // PyTorch [i,f,g,o] gate layout
        float ve = (k < E_) ? eWih[r * E_ + k] : eWhh[r * H_ + (k - E_)];
        float vd = (k < E_) ? dWih[r * E_ + k] : dWhh[r * H_ + (k - E_)];
        g_Wf[0][i] = __float2half_rn(ve);
        g_Wf[1][i] = __float2half_rn(vd);
    }
    for (long long i = t0; i < NCOL_; i += st) {
        int g = (int)i & 3, n = (int)i >> 2;
        int r = g * H_ + n;
        g_bias[0][i] = eBih[r] + eBhh[r];
        g_bias[1][i] = dBih[r] + dBhh[r];
    }
    for (long long i = t0; i < (long long)V_TGT_ * H_; i += st)
        g_WoVf[i] = __float2half_rn(Wout[i]);    // Wout is [V][H] = [n][k]
    __half z = __float2half_rn(0.0f);
    for (long long i = t0; i < BH_; i += st) {
        g_hf[0][i] = z;
        g_c[i] = 0.0f;
    }
}

// ---------------------------------------------------------------------------
// Stage loader: kt in [0,10), buffer = kt % 3. A 16KB + W 16KB, SW128 rows.
// ---------------------------------------------------------------------------
__device__ __forceinline__ void load_tile(uint32_t base, int kt, int m0, int n0p, int tid,
    const __half* __restrict__ Xf, const __half* __restrict__ Hf,
    const __half* __restrict__ Wf)
{
    const int kofs = kt * 64;
    uint32_t sb = base + (uint32_t)(kt % 3) * STAGE_;
    #pragma unroll
    for (int i = 0; i < 4; i++) {                 // A: 128 rows x 8 chunks(16B)
        int idx = tid + i * 256;
        int row = idx >> 3, c = idx & 7;
        uint32_t doff = (uint32_t)(row * 128 + ((c * 16) ^ ((row & 7) << 4)));
        const __half* src = (kt < 2)
            ? Xf + (size_t)(m0 + row) * E_ + kofs + c * 8
            : Hf + (size_t)(m0 + row) * H_ + (kofs - E_) + c * 8;
        cp16(sb + doff, src);
    }
    #pragma unroll
    for (int i = 0; i < 4; i++) {                 // W: 128 rows x 8 chunks
        int idx = tid + i * 256;
        int row = idx >> 3, c = idx & 7;
        uint32_t doff = (uint32_t)(row * 128 + ((c * 16) ^ ((row & 7) << 4)));
        cp16(sb + OFF_W_ + doff, Wf + (size_t)(n0p + row) * KC_ + kofs + c * 8);
    }
    asm volatile("cp.async.commit_group;" ::: "memory");
}

// ---------------------------------------------------------------------------
// Fused LSTM step: fp16 mma, fp32 accum; 3-deep cp.async pipeline.
// ---------------------------------------------------------------------------
__global__ __launch_bounds__(256, 2)
void lstm_step(int ss, int dir, int par, const int* __restrict__ src_len)
{
    extern __shared__ char dyn_smem[];
    __shared__ __align__(16) float bias_s[BN_];

    const int tid  = threadIdx.x;
    const int lane = tid & 31;
    const int wid  = tid >> 5;
    const int warp_m = wid & 1;          // 64-row half
    const int warp_n = wid >> 1;         // 0..3 -> 32-col slice
    const int m0  = blockIdx.x * BM_;
    const int n0p = blockIdx.y * BN_;

    uint32_t base = (smem_u32(dyn_smem) + 1023u) & ~1023u;

    const __half* Xf   = g_Xf + (size_t)ss * XSTEP_;
    const __half* Wf   = g_Wf[dir];
    const __half* hf_s = g_hf[par];
    __half*       hf_d = g_hf[par ^ 1];

    if (tid < BN_) bias_s[tid] = g_bias[dir][n0p + tid];

    float acc[4][4][4];
    #pragma unroll
    for (int mt = 0; mt < 4; mt++)
        #pragma unroll
        for (int nt = 0; nt < 4; nt++)
            #pragma unroll
            for (int q = 0; q < 4; q++) acc[mt][nt][q] = 0.0f;

    uint32_t aRow[4], aXor[4];
    #pragma unroll
    for (int mt = 0; mt < 4; mt++) {
        int row = warp_m * 64 + mt * 16 + (lane & 15);
        aRow[mt] = (uint32_t)(row * 128 + ((lane >> 4) * 16));
        aXor[mt] = (uint32_t)((row & 7) << 4);
    }
    uint32_t bRow[2], bXor[2];
    #pragma unroll
    for (int bt = 0; bt < 2; bt++) {
        int row = warp_n * 32 + bt * 16 + ((lane >> 4) & 1) * 8 + (lane & 7);
        bRow[bt] = (uint32_t)(row * 128 + (((lane >> 3) & 1) * 16));
        bXor[bt] = (uint32_t)((row & 7) << 4);
    }

    // 3-deep prologue
    load_tile(base, 0, m0, n0p, tid, Xf, hf_s, Wf);
    load_tile(base, 1, m0, n0p, tid, Xf, hf_s, Wf);
    load_tile(base, 2, m0, n0p, tid, Xf, hf_s, Wf);

    for (int s = 0; s < NKT_; s++) {
        PIPE_WAIT(s, NKT_);
        __syncthreads();

        const uint32_t Ab = base + (uint32_t)(s % 3) * STAGE_;
        const uint32_t Wb = Ab + OFF_W_;

        #pragma unroll
        for (int k16 = 0; k16 < 4; k16++) {
            uint32_t kb = (uint32_t)(k16 * 32);
            uint32_t a[4][4], w[2][4];
            #pragma unroll
            for (int mt = 0; mt < 4; mt++)
                ldm_x4(a[mt], Ab + ((aRow[mt] + kb) ^ aXor[mt]));
            #pragma unroll
            for (int bt = 0; bt < 2; bt++)
                ldm_x4(w[bt], Wb + ((bRow[bt] + kb) ^ bXor[bt]));
            #pragma unroll
            for (int mt = 0; mt < 4; mt++)
                #pragma unroll
                for (int nt = 0; nt < 4; nt++) {
                    int bt = nt >> 1, q = nt & 1;
                    mma16816(acc[mt][nt], a[mt], w[bt][2 * q], w[bt][2 * q + 1]);
                }
        }
        __syncthreads();
        if (s + 3 < NKT_)
            load_tile(base, s + 3, m0, n0p, tid, Xf, hf_s, Wf);
    }

    // ------------------ epilogue: C -> smem (stage area drained) -------------
    float* Cs;
    {
        uintptr_t g = (uintptr_t)dyn_smem;
        uintptr_t delta = (uintptr_t)(base - smem_u32(dyn_smem));
        Cs = (float*)(g + delta);
    }
    const int CSTRIDE = 132;

    #pragma unroll
    for (int mt = 0; mt < 4; mt++)
        #pragma unroll
        for (int nt = 0; nt < 4; nt++) {
            int r   = warp_m * 64 + mt * 16 + (lane >> 2);
            int col = warp_n * 32 + nt * 8 + 2 * (lane & 3);
            Cs[r * CSTRIDE + col]           = acc[mt][nt][0];
            Cs[r * CSTRIDE + col + 1]       = acc[mt][nt][1];
            Cs[(r + 8) * CSTRIDE + col]     = acc[mt][nt][2];
            Cs[(r + 8) * CSTRIDE + col + 1] = acc[mt][nt][3];
        }
    __syncthreads();

    // 128 rows x 32 h-units = 4096 cells, 16 per thread
    const int hq0 = n0p >> 2;
    #pragma unroll
    for (int i = 0; i < 16; i++) {
        int cell = i * 256 + tid;
        int m_l = cell >> 5;
        int h_l = cell & 31;
        int m = m0 + m_l;
        size_t idx = (size_t)m * H_ + hq0 + h_l;
        bool frozen = (src_len != nullptr) && (ss >= src_len[m]);
        if (frozen) {
            hf_d[idx] = hf_s[idx];
        } else {
            const float* gp = &Cs[m_l * CSTRIDE + h_l * 4];
            float gi = gp[0] + bias_s[h_l * 4 + 0];
            float gf = gp[1] + bias_s[h_l * 4 + 1];
            float gg = gp[2] + bias_s[h_l * 4 + 2];
            float go = gp[3] + bias_s[h_l * 4 + 3];
            float cc = fsig(gf) * g_c[idx] + fsig(gi) * ftanh(gg);
            float hv = fsig(go) * ftanh(cc);
            g_c[idx] = cc;
            __half hh = __float2half_rn(hv);
            hf_d[idx] = hh;
            if (dir) g_hsf[(size_t)(ss - 32) * BH_ + idx] = hh;
        }
    }
}

// ---------------------------------------------------------------------------
// Logits: (131072, 512) @ (512, 128) + b_out; same 3-deep pipeline.
// ---------------------------------------------------------------------------
#define LNKT_ 8   // 512 / 64

__device__ __forceinline__ void load_tile_lg(uint32_t base, int kt, int m0, int tid)
{
    const int kofs = kt * 64;
    uint32_t sb = base + (uint32_t)(kt % 3) * STAGE_;
    #pragma unroll
    for (int i = 0; i < 4; i++) {
        int idx = tid + i * 256;
        int row = idx >> 3, c = idx & 7;
        uint32_t doff = (uint32_t)(row * 128 + ((c * 16) ^ ((row & 7) << 4)));
        cp16(sb + doff, g_hsf + (size_t)(m0 + row) * H_ + kofs + c * 8);
    }
    #pragma unroll
    for (int i = 0; i < 4; i++) {
        int idx = tid + i * 256;
        int row = idx >> 3, c = idx & 7;
        uint32_t doff = (uint32_t)(row * 128 + ((c * 16) ^ ((row & 7) << 4)));
        cp16(sb + OFF_W_ + doff, g_WoVf + (size_t)row * H_ + kofs + c * 8);
    }
    asm volatile("cp.async.commit_group;" ::: "memory");
}

__global__ __launch_bounds__(256, 2)
void logits_kernel(const float* __restrict__ b_out, float* __restrict__ out)
{
    extern __shared__ char dyn_smem[];

    const int tid  = threadIdx.x;
    const int lane = tid & 31;
    const int wid  = tid >> 5;
    const int warp_m = wid & 1;
    const int warp_n = wid >> 1;
    const int m0 = blockIdx.x * 128;

    uint32_t base = (smem_u32(dyn_smem) + 1023u) & ~1023u;

    float acc[4][4][4];
    #pragma unroll
    for (int mt = 0; mt < 4; mt++)
        #pragma unroll
        for (int nt = 0; nt < 4; nt++)
            #pragma unroll
            for (int q = 0; q < 4; q++) acc[mt][nt][q] = 0.0f;

    uint32_t aRow[4], aXor[4];
    #pragma unroll
    for (int mt = 0; mt < 4; mt++) {
        int row = warp_m * 64 + mt * 16 + (lane & 15);
        aRow[mt] = (uint32_t)(row * 128 + ((lane >> 4) * 16));
        aXor[mt] = (uint32_t)((row & 7) << 4);
    }
    uint32_t bRow[2], bXor[2];
    #pragma unroll
    for (int bt = 0; bt < 2; bt++) {
        int row = warp_n * 32 + bt * 16 + ((lane >> 4) & 1) * 8 + (lane & 7);
        bRow[bt] = (uint32_t)(row * 128 + (((lane >> 3) & 1) * 16));
        bXor[bt] = (uint32_t)((row & 7) << 4);
    }

    load_tile_lg(base, 0, m0, tid);
    load_tile_lg(base, 1, m0, tid);
    load_tile_lg(base, 2, m0, tid);

    for (int s = 0; s < LNKT_; s++) {
        PIPE_WAIT(s, LNKT_);
        __syncthreads();

        const uint32_t Ab = base + (uint32_t)(s % 3) * STAGE_;
        const uint32_t Wb = Ab + OFF_W_;

        #pragma unroll
        for (int k16 = 0; k16 < 4; k16++) {
            uint32_t kb = (uint32_t)(k16 * 32);
            uint32_t a[4][4], w[2][4];
            #pragma unroll
            for (int mt = 0; mt < 4; mt++)
                ldm_x4(a[mt], Ab + ((aRow[mt] + kb) ^ aXor[mt]));
            #pragma unroll
            for (int bt = 0; bt < 2; bt++)
                ldm_x4(w[bt], Wb + ((bRow[bt] + kb) ^ bXor[bt]));
            #pragma unroll
            for (int mt = 0; mt < 4; mt++)
                #pragma unroll
                for (int nt = 0; nt < 4; nt++) {
                    int bt = nt >> 1, q = nt & 1;
                    mma16816(acc[mt][nt], a[mt], w[bt][2 * q], w[bt][2 * q + 1]);
                }
        }
        __syncthreads();
        if (s + 3 < LNKT_) load_tile_lg(base, s + 3, m0, tid);
    }

    // epilogue: C -> smem (stage area drained) -> out (coalesced over v)
    float* Cs;
    {
        uintptr_t g = (uintptr_t)dyn_smem;
        uintptr_t delta = (uintptr_t)(base - smem_u32(dyn_smem));
        Cs = (float*)(g + delta);
    }
    const int CSTRIDE = 132;
    #pragma unroll
    for (int mt = 0; mt < 4; mt++)
        #pragma unroll
        for (int nt = 0; nt < 4; nt++) {
            int r   = warp_m * 64 + mt * 16 + (lane >> 2);
            int col = warp_n * 32 + nt * 8 + 2 * (lane & 3);
            Cs[r * CSTRIDE + col]           = acc[mt][nt][0];
            Cs[r * CSTRIDE + col + 1]       = acc[mt][nt][1];
            Cs[(r + 8) * CSTRIDE + col]     = acc[mt][nt][2];
            Cs[(r + 8) * CSTRIDE + col + 1] = acc[mt][nt][3];
        }
    __syncthreads();

    #pragma unroll
    for (int i = 0; i < 64; i++) {
        int cell = i * 256 + tid;
        int r = cell >> 7;
        int v = cell & 127;
        int m_g = m0 + r;                 // m_g = t*4096 + b
        int b  = m_g & (B_ - 1);
        int tt = m_g >> 12;
        out[((size_t)b * S_ + tt) * V_TGT_ + v] = Cs[r * CSTRIDE + v] + b_out[v];
    }
}

// ---------------------------------------------------------------------------
extern "C" void kernel_launch(void* const* d_in, const int* in_sizes, int n_in,
                              void* d_out, int out_size)
{
    (void)in_sizes; (void)n_in; (void)out_size;
    const int*   src_seq = (const int*)  d_in[0];
    const int*   src_len = (const int*)  d_in[1];
    const int*   tgt_seq = (const int*)  d_in[2];
    const float* emb_src = (const float*)d_in[3];
    const float* eWih    = (const float*)d_in[4];
    const float* eWhh    = (const float*)d_in[5];
    const float* eBih    = (const float*)d_in[6];
    const float* eBhh    = (const float*)d_in[7];
    const float* emb_tgt = (const float*)d_in[8];
    const float* dWih    = (const float*)d_in[9];
    const float* dWhh    = (const float*)d_in[10];
    const float* dBih    = (const float*)d_in[11];
    const float* dBhh    = (const float*)d_in[12];
    const float* Wout    = (const float*)d_in[13];
    const float* bout    = (const float*)d_in[14];
    float*       out     = (float*)d_out;

    cudaFuncSetAttribute(lstm_step, cudaFuncAttributeMaxDynamicSharedMemorySize, SMEM_DYN_);
    cudaFuncSetAttribute(logits_kernel, cudaFuncAttributeMaxDynamicSharedMemorySize, SMEM_DYN_);

    prep_kernel<<<4096, 256>>>(src_seq, tgt_seq, emb_src, emb_tgt,
                               eWih, eWhh, eBih, eBhh,
                               dWih, dWhh, dBih, dBhh, Wout);

    dim3 grid(B_ / BM_, NCOL_ / BN_);   // (32, 16) = 512 CTAs, 2/SM
    for (int s = 0; s < 32; s++)
        lstm_step<<<grid, 256, SMEM_DYN_>>>(s, 0, s & 1, src_len);
    for (int s = 32; s < 64; s++)
        lstm_step<<<grid, 256, SMEM_DYN_>>>(s, 1, s & 1, nullptr);

    logits_kernel<<<(B_ * S_) / 128, 256, SMEM_DYN_>>>(bout, out);
}

// round 16
// speedup vs baseline: 1.1477x; 1.0429x over previous
#include <cuda_runtime.h>
#include <cuda_fp16.h>
#include <cstdint>
#include <math.h>

#define B_      4096
#define S_      32
#define E_      128
#define H_      512
#define V_TGT_  128
#define NCOL_   2048          // 4*H, gate-interleaved col' = h*4 + gate
#define KC_     640           // E + H
#define SOS_    1
#define NSTEP_  64
#define BH_     (B_ * H_)
#define XSTEP_  (B_ * E_)

// LSTM step: 128x128 tile, 256 thr (8 warps, warp tile 64x32), BK=64,
// 3-buffer depth-2 cp.async pipeline (single sync/stage), 2 CTAs/SM, PDL.
#define BM_     128
#define BN_     128
#define NKT_    10            // 640 / 64
#define STAGE_  32768         // A 16K | W 16K
#define OFF_W_  16384
#define SMEM_DYN_ 99328       // 1K align + 3*32K stages (C 128x132 overlays)

// ---------------------------------------------------------------------------
// Device scratch (static; no allocations allowed)
// ---------------------------------------------------------------------------
__device__ __align__(256) __half g_Xf[NSTEP_ * XSTEP_];      // emb slice, all steps
__device__ __align__(256) __half g_Wf[2][NCOL_ * KC_];       // [dir][n'][k]
__device__ __align__(256) float  g_bias[2][NCOL_];
__device__ __align__(256) __half g_hf[2][BH_];               // ping-pong hidden
__device__ __align__(256) float  g_c[BH_];
__device__ __align__(256) __half g_hsf[S_ * BH_];            // decoder hiddens
__device__ __align__(256) __half g_WoVf[V_TGT_ * H_];        // [v][k]

// ---------------------------------------------------------------------------
__device__ __forceinline__ uint32_t smem_u32(const void* p) {
    uint32_t a;
    asm("{ .reg .u64 t; cvta.to.shared.u64 t, %1; cvt.u32.u64 %0, t; }" : "=r"(a) : "l"(p));
    return a;
}
__device__ __forceinline__ void cp16(uint32_t dst, const void* src) {
    asm volatile("cp.async.cg.shared.global [%0], [%1], 16;" :: "r"(dst), "l"(src));
}
__device__ __forceinline__ void ldm_x4(uint32_t* r, uint32_t addr) {
    asm volatile("ldmatrix.sync.aligned.m8n8.x4.shared.b16 {%0,%1,%2,%3}, [%4];"
        : "=r"(r[0]), "=r"(r[1]), "=r"(r[2]), "=r"(r[3]) : "r"(addr));
}
__device__ __forceinline__ void mma16816(float* c, const uint32_t* a, uint32_t b0, uint32_t b1) {
    asm volatile("mma.sync.aligned.m16n8k16.row.col.f32.f16.f16.f32 "
        "{%0,%1,%2,%3}, {%4,%5,%6,%7}, {%8,%9}, {%0,%1,%2,%3};"
        : "+f"(c[0]), "+f"(c[1]), "+f"(c[2]), "+f"(c[3])
        : "r"(a[0]), "r"(a[1]), "r"(a[2]), "r"(a[3]), "r"(b0), "r"(b1));
}
__device__ __forceinline__ float fsig(float x)  { return __fdividef(1.0f, 1.0f + __expf(-x)); }
__device__ __forceinline__ float ftanh(float x) { return 1.0f - __fdividef(2.0f, __expf(2.0f * x) + 1.0f); }

// wait for group s (depth-2 in flight): s < NITER-1 -> one group may pend.
#define PIPE_WAIT2(s, NITER) do { \
    if ((s) < (NITER) - 1) asm volatile("cp.async.wait_group 1;" ::: "memory"); \
    else                   asm volatile("cp.async.wait_group 0;" ::: "memory"); \
} while (0)

// ---------------------------------------------------------------------------
// Prep: fp16 weights (gate-interleaved [n'][k]), fp16 embedding slices for all
// 64 steps, summed biases, fp16 WoutT, zeroed state.
// ---------------------------------------------------------------------------
__global__ void prep_kernel(const int* __restrict__ src_seq, const int* __restrict__ tgt_seq,
                            const float* __restrict__ emb_src, const float* __restrict__ emb_tgt,
                            const float* __restrict__ eWih, const float* __restrict__ eWhh,
                            const float* __restrict__ eBih, const float* __restrict__ eBhh,
                            const float* __restrict__ dWih, const float* __restrict__ dWhh,
                            const float* __restrict__ dBih, const float* __restrict__ dBhh,
                            const float* __restrict__ Wout)
{
    const long long t0 = (long long)blockIdx.x * blockDim.x + threadIdx.x;
    const long long st = (long long)gridDim.x * blockDim.x;

    for (long long i = t0; i < (long long)NSTEP_ * XSTEP_; i += st) {
        int k = (int)(i & 127);
        long long sm = i >> 7;
        int m = (int)(sm & (B_ - 1));
        int s = (int)(sm >> 12);
        int tok; const float* emb;
        if (s < 32)       { tok = src_seq[m * S_ + s]; emb = emb_src; }
        else if (s == 32) { tok = SOS_;                emb = emb_tgt; }
        else              { tok = tgt_seq[m * S_ + (s - 33)]; emb = emb_tgt; }
        g_Xf[i] = __float2half_rn(emb[tok * E_ + k]);
    }
    for (long long i = t0; i < (long long)NCOL_ * KC_; i += st) {
        int np = (int)(i / KC_);
        int k  = (int)(i - (long long)np * KC_);
        int g = np & 3, n = np >> 2;
        int r = g * H_ + n;                       // PyTorch [i,f,g,o] gate layout
        float ve = (k < E_) ? eWih[r * E_ + k] : eWhh[r * H_ + (k - E_)];
        float vd = (k < E_) ? dWih[r * E_ + k] : dWhh[r * H_ + (k - E_)];
        g_Wf[0][i] = __float2half_rn(ve);
        g_Wf[1][i] = __float2half_rn(vd);
    }
    for (long long i = t0; i < NCOL_; i += st) {
        int g = (int)i & 3, n = (int)i >> 2;
        int r = g * H_ + n;
        g_bias[0][i] = eBih[r] + eBhh[r];
        g_bias[1][i] = dBih[r] + dBhh[r];
    }
    for (long long i = t0; i < (long long)V_TGT_ * H_; i += st)
        g_WoVf[i] = __float2half_rn(Wout[i]);    // Wout is [V][H] = [n][k]
    __half z = __float2half_rn(0.0f);
    for (long long i = t0; i < BH_; i += st) {
        g_hf[0][i] = z;
        g_c[i] = 0.0f;
    }
}

// ---------------------------------------------------------------------------
// Stage loader: kt in [0,10), buffer = kt % 3. A 16KB + W 16KB, SW128 rows.
// kt 0,1 read ONLY X and W (h-independent) -> safe before griddepcontrol.wait.
// ---------------------------------------------------------------------------
__device__ __forceinline__ void load_tile(uint32_t base, int kt, int m0, int n0p, int tid,
    const __half* __restrict__ Xf, const __half* __restrict__ Hf,
    const __half* __restrict__ Wf)
{
    const int kofs = kt * 64;
    uint32_t sb = base + (uint32_t)(kt % 3) * STAGE_;
    #pragma unroll
    for (int i = 0; i < 4; i++) {                 // A: 128 rows x 8 chunks(16B)
        int idx = tid + i * 256;
        int row = idx >> 3, c = idx & 7;
        uint32_t doff = (uint32_t)(row * 128 + ((c * 16) ^ ((row & 7) << 4)));
        const __half* src = (kt < 2)
            ? Xf + (size_t)(m0 + row) * E_ + kofs + c * 8
            : Hf + (size_t)(m0 + row) * H_ + (kofs - E_) + c * 8;
        cp16(sb + doff, src);
    }
    #pragma unroll
    for (int i = 0; i < 4; i++) {                 // W: 128 rows x 8 chunks
        int idx = tid + i * 256;
        int row = idx >> 3, c = idx & 7;
        uint32_t doff = (uint32_t)(row * 128 + ((c * 16) ^ ((row & 7) << 4)));
        cp16(sb + OFF_W_ + doff, Wf + (size_t)(n0p + row) * KC_ + kofs + c * 8);
    }
    asm volatile("cp.async.commit_group;" ::: "memory");
}

// ---------------------------------------------------------------------------
// Fused LSTM step: fp16 mma, fp32 accum; PDL + 3-buffer depth-2 pipeline.
// ---------------------------------------------------------------------------
__global__ __launch_bounds__(256, 2)
void lstm_step(int ss, int dir, int par, const int* __restrict__ src_len)
{
    extern __shared__ char dyn_smem[];
    __shared__ __align__(16) float bias_s[BN_];

    // Signal the dependent (next step) that it may begin its h-independent
    // prologue while this kernel is still running.
    asm volatile("griddepcontrol.launch_dependents;");

    const int tid  = threadIdx.x;
    const int lane = tid & 31;
    const int wid  = tid >> 5;
    const int warp_m = wid & 1;          // 64-row half
    const int warp_n = wid >> 1;         // 0..3 -> 32-col slice
    const int m0  = blockIdx.x * BM_;
    const int n0p = blockIdx.y * BN_;

    uint32_t base = (smem_u32(dyn_smem) + 1023u) & ~1023u;

    const __half* Xf   = g_Xf + (size_t)ss * XSTEP_;
    const __half* Wf   = g_Wf[dir];
    const __half* hf_s = g_hf[par];
    __half*       hf_d = g_hf[par ^ 1];

    if (tid < BN_) bias_s[tid] = g_bias[dir][n0p + tid];

    float acc[4][4][4];
    #pragma unroll
    for (int mt = 0; mt < 4; mt++)
        #pragma unroll
        for (int nt = 0; nt < 4; nt++)
            #pragma unroll
            for (int q = 0; q < 4; q++) acc[mt][nt][q] = 0.0f;

    uint32_t aRow[4], aXor[4];
    #pragma unroll
    for (int mt = 0; mt < 4; mt++) {
        int row = warp_m * 64 + mt * 16 + (lane & 15);
        aRow[mt] = (uint32_t)(row * 128 + ((lane >> 4) * 16));
        aXor[mt] = (uint32_t)((row & 7) << 4);
    }
    uint32_t bRow[2], bXor[2];
    #pragma unroll
    for (int bt = 0; bt < 2; bt++) {
        int row = warp_n * 32 + bt * 16 + ((lane >> 4) & 1) * 8 + (lane & 7);
        bRow[bt] = (uint32_t)(row * 128 + (((lane >> 3) & 1) * 16));
        bXor[bt] = (uint32_t)((row & 7) << 4);
    }

    // h-independent prologue (X-only stages 0,1 + their W): overlaps the
    // predecessor step's epilogue/drain under PDL.
    load_tile(base, 0, m0, n0p, tid, Xf, hf_s, Wf);
    load_tile(base, 1, m0, n0p, tid, Xf, hf_s, Wf);

    // Wait for the predecessor grid to fully complete before touching h / c.
    asm volatile("griddepcontrol.wait;");

    for (int s = 0; s < NKT_; s++) {
        PIPE_WAIT2(s, NKT_);
        __syncthreads();
        // prefetch s+2 into buffer (s+2)%3 (held stage s-1; all threads done)
        if (s + 2 < NKT_)
            load_tile(base, s + 2, m0, n0p, tid, Xf, hf_s, Wf);

        const uint32_t Ab = base + (uint32_t)(s % 3) * STAGE_;
        const uint32_t Wb = Ab + OFF_W_;

        #pragma unroll
        for (int k16 = 0; k16 < 4; k16++) {
            uint32_t kb = (uint32_t)(k16 * 32);
            uint32_t a[4][4], w[2][4];
            #pragma unroll
            for (int mt = 0; mt < 4; mt++)
                ldm_x4(a[mt], Ab + ((aRow[mt] + kb) ^ aXor[mt]));
            #pragma unroll
            for (int bt = 0; bt < 2; bt++)
                ldm_x4(w[bt], Wb + ((bRow[bt] + kb) ^ bXor[bt]));
            #pragma unroll
            for (int mt = 0; mt < 4; mt++)
                #pragma unroll
                for (int nt = 0; nt < 4; nt++) {
                    int bt = nt >> 1, q = nt & 1;
                    mma16816(acc[mt][nt], a[mt], w[bt][2 * q], w[bt][2 * q + 1]);
                }
        }
    }
    __syncthreads();   // all warps done reading stage buffers before C overlay

    // ------------------ epilogue: C -> smem (stage area drained) -------------
    float* Cs;
    {
        uintptr_t g = (uintptr_t)dyn_smem;
        uintptr_t delta = (uintptr_t)(base - smem_u32(dyn_smem));
        Cs = (float*)(g + delta);
    }
    const int CSTRIDE = 132;

    #pragma unroll
    for (int mt = 0; mt < 4; mt++)
        #pragma unroll
        for (int nt = 0; nt < 4; nt++) {
            int r   = warp_m * 64 + mt * 16 + (lane >> 2);
            int col = warp_n * 32 + nt * 8 + 2 * (lane & 3);
            Cs[r * CSTRIDE + col]           = acc[mt][nt][0];
            Cs[r * CSTRIDE + col + 1]       = acc[mt][nt][1];
            Cs[(r + 8) * CSTRIDE + col]     = acc[mt][nt][2];
            Cs[(r + 8) * CSTRIDE + col + 1] = acc[mt][nt][3];
        }
    __syncthreads();

    // 128 rows x 32 h-units = 4096 cells, 16 per thread
    const int hq0 = n0p >> 2;
    #pragma unroll
    for (int i = 0; i < 16; i++) {
        int cell = i * 256 + tid;
        int m_l = cell >> 5;
        int h_l = cell & 31;
        int m = m0 + m_l;
        size_t idx = (size_t)m * H_ + hq0 + h_l;
        bool frozen = (src_len != nullptr) && (ss >= src_len[m]);
        if (frozen) {
            hf_d[idx] = hf_s[idx];
        } else {
            const float* gp = &Cs[m_l * CSTRIDE + h_l * 4];
            float gi = gp[0] + bias_s[h_l * 4 + 0];
            float gf = gp[1] + bias_s[h_l * 4 + 1];
            float gg = gp[2] + bias_s[h_l * 4 + 2];
            float go = gp[3] + bias_s[h_l * 4 + 3];
            float cc = fsig(gf) * g_c[idx] + fsig(gi) * ftanh(gg);
            float hv = fsig(go) * ftanh(cc);
            g_c[idx] = cc;
            __half hh = __float2half_rn(hv);
            hf_d[idx] = hh;
            if (dir) g_hsf[(size_t)(ss - 32) * BH_ + idx] = hh;
        }
    }
}

// ---------------------------------------------------------------------------
// Logits: (131072, 512) @ (512, 128) + b_out; 3-buffer depth-2 pipeline.
// ---------------------------------------------------------------------------
#define LNKT_ 8   // 512 / 64

__device__ __forceinline__ void load_tile_lg(uint32_t base, int kt, int m0, int tid)
{
    const int kofs = kt * 64;
    uint32_t sb = base + (uint32_t)(kt % 3) * STAGE_;
    #pragma unroll
    for (int i = 0; i < 4; i++) {
        int idx = tid + i * 256;
        int row = idx >> 3, c = idx & 7;
        uint32_t doff = (uint32_t)(row * 128 + ((c * 16) ^ ((row & 7) << 4)));
        cp16(sb + doff, g_hsf + (size_t)(m0 + row) * H_ + kofs + c * 8);
    }
    #pragma unroll
    for (int i = 0; i < 4; i++) {
        int idx = tid + i * 256;
        int row = idx >> 3, c = idx & 7;
        uint32_t doff = (uint32_t)(row * 128 + ((c * 16) ^ ((row & 7) << 4)));
        cp16(sb + OFF_W_ + doff, g_WoVf + (size_t)row * H_ + kofs + c * 8);
    }
    asm volatile("cp.async.commit_group;" ::: "memory");
}

__global__ __launch_bounds__(256, 2)
void logits_kernel(const float* __restrict__ b_out, float* __restrict__ out)
{
    extern __shared__ char dyn_smem[];

    const int tid  = threadIdx.x;
    const int lane = tid & 31;
    const int wid  = tid >> 5;
    const int warp_m = wid & 1;
    const int warp_n = wid >> 1;
    const int m0 = blockIdx.x * 128;

    uint32_t base = (smem_u32(dyn_smem) + 1023u) & ~1023u;

    float acc[4][4][4];
    #pragma unroll
    for (int mt = 0; mt < 4; mt++)
        #pragma unroll
        for (int nt = 0; nt < 4; nt++)
            #pragma unroll
            for (int q = 0; q < 4; q++) acc[mt][nt][q] = 0.0f;

    uint32_t aRow[4], aXor[4];
    #pragma unroll
    for (int mt = 0; mt < 4; mt++) {
        int row = warp_m * 64 + mt * 16 + (lane & 15);
        aRow[mt] = (uint32_t)(row * 128 + ((lane >> 4) * 16));
        aXor[mt] = (uint32_t)((row & 7) << 4);
    }
    uint32_t bRow[2], bXor[2];
    #pragma unroll
    for (int bt = 0; bt < 2; bt++) {
        int row = warp_n * 32 + bt * 16 + ((lane >> 4) & 1) * 8 + (lane & 7);
        bRow[bt] = (uint32_t)(row * 128 + (((lane >> 3) & 1) * 16));
        bXor[bt] = (uint32_t)((row & 7) << 4);
    }

    load_tile_lg(base, 0, m0, tid);
    load_tile_lg(base, 1, m0, tid);

    for (int s = 0; s < LNKT_; s++) {
        PIPE_WAIT2(s, LNKT_);
        __syncthreads();
        if (s + 2 < LNKT_) load_tile_lg(base, s + 2, m0, tid);

        const uint32_t Ab = base + (uint32_t)(s % 3) * STAGE_;
        const uint32_t Wb = Ab + OFF_W_;

        #pragma unroll
        for (int k16 = 0; k16 < 4; k16++) {
            uint32_t kb = (uint32_t)(k16 * 32);
            uint32_t a[4][4], w[2][4];
            #pragma unroll
            for (int mt = 0; mt < 4; mt++)
                ldm_x4(a[mt], Ab + ((aRow[mt] + kb) ^ aXor[mt]));
            #pragma unroll
            for (int bt = 0; bt < 2; bt++)
                ldm_x4(w[bt], Wb + ((bRow[bt] + kb) ^ bXor[bt]));
            #pragma unroll
            for (int mt = 0; mt < 4; mt++)
                #pragma unroll
                for (int nt = 0; nt < 4; nt++) {
                    int bt = nt >> 1, q = nt & 1;
                    mma16816(acc[mt][nt], a[mt], w[bt][2 * q], w[bt][2 * q + 1]);
                }
        }
    }
    __syncthreads();   // drain stage-buffer reads before C overlay

    float* Cs;
    {
        uintptr_t g = (uintptr_t)dyn_smem;
        uintptr_t delta = (uintptr_t)(base - smem_u32(dyn_smem));
        Cs = (float*)(g + delta);
    }
    const int CSTRIDE = 132;
    #pragma unroll
    for (int mt = 0; mt < 4; mt++)
        #pragma unroll
        for (int nt = 0; nt < 4; nt++) {
            int r   = warp_m * 64 + mt * 16 + (lane >> 2);
            int col = warp_n * 32 + nt * 8 + 2 * (lane & 3);
            Cs[r * CSTRIDE + col]           = acc[mt][nt][0];
            Cs[r * CSTRIDE + col + 1]       = acc[mt][nt][1];
            Cs[(r + 8) * CSTRIDE + col]     = acc[mt][nt][2];
            Cs[(r + 8) * CSTRIDE + col + 1] = acc[mt][nt][3];
        }
    __syncthreads();

    #pragma unroll
    for (int i = 0; i < 64; i++) {
        int cell = i * 256 + tid;
        int r = cell >> 7;
        int v = cell & 127;
        int m_g = m0 + r;                 // m_g = t*4096 + b
        int b  = m_g & (B_ - 1);
        int tt = m_g >> 12;
        out[((size_t)b * S_ + tt) * V_TGT_ + v] = Cs[r * CSTRIDE + v] + b_out[v];
    }
}

// ---------------------------------------------------------------------------
extern "C" void kernel_launch(void* const* d_in, const int* in_sizes, int n_in,
                              void* d_out, int out_size)
{
    (void)in_sizes; (void)n_in; (void)out_size;
    const int*   src_seq = (const int*)  d_in[0];
    const int*   src_len = (const int*)  d_in[1];
    const int*   tgt_seq = (const int*)  d_in[2];
    const float* emb_src = (const float*)d_in[3];
    const float* eWih    = (const float*)d_in[4];
    const float* eWhh    = (const float*)d_in[5];
    const float* eBih    = (const float*)d_in[6];
    const float* eBhh    = (const float*)d_in[7];
    const float* emb_tgt = (const float*)d_in[8];
    const float* dWih    = (const float*)d_in[9];
    const float* dWhh    = (const float*)d_in[10];
    const float* dBih    = (const float*)d_in[11];
    const float* dBhh    = (const float*)d_in[12];
    const float* Wout    = (const float*)d_in[13];
    const float* bout    = (const float*)d_in[14];
    float*       out     = (float*)d_out;

    cudaFuncSetAttribute(lstm_step, cudaFuncAttributeMaxDynamicSharedMemorySize, SMEM_DYN_);
    cudaFuncSetAttribute(logits_kernel, cudaFuncAttributeMaxDynamicSharedMemorySize, SMEM_DYN_);

    prep_kernel<<<4096, 256>>>(src_seq, tgt_seq, emb_src, emb_tgt,
                               eWih, eWhh, eBih, eBhh,
                               dWih, dWhh, dBih, dBhh, Wout);

    dim3 grid(B_ / BM_, NCOL_ / BN_);   // (32, 16) = 512 CTAs, 2/SM

    // step 0: normal launch (serializes after prep)
    lstm_step<<<grid, 256, SMEM_DYN_>>>(0, 0, 0, src_len);

    // steps 1..63: PDL — may begin h-independent prologue while predecessor runs
    for (int s = 1; s < 64; s++) {
        int dir = (s < 32) ? 0 : 1;
        const int* len = (s < 32) ? src_len : nullptr;

        cudaLaunchConfig_t cfg = {};
        cfg.gridDim = grid;
        cfg.blockDim = dim3(256, 1, 1);
        cfg.dynamicSmemBytes = SMEM_DYN_;
        cfg.stream = 0;
        cudaLaunchAttribute attr[1];
        attr[0].id = cudaLaunchAttributeProgrammaticStreamSerialization;
        attr[0].val.programmaticStreamSerializationAllowed = 1;
        cfg.attrs = attr;
        cfg.numAttrs = 1;
        cudaLaunchKernelEx(&cfg, lstm_step, s, dir, s & 1, len);
    }

    logits_kernel<<<(B_ * S_) / 128, 256, SMEM_DYN_>>>(bout, out);
}

// round 17
// speedup vs baseline: 1.2960x; 1.1292x over previous
#include <cuda_runtime.h>
#include <cuda_fp16.h>
#include <cstdint>
#include <math.h>

#define B_      4096
#define S_      32
#define E_      128
#define H_      512
#define V_TGT_  128
#define NCOL_   2048          // 4*H, gate-interleaved col' = h*4 + gate
#define KC_     640           // E + H
#define SOS_    1
#define NSTEP_  64
#define BH_     (B_ * H_)
#define XSTEP_  (B_ * E_)

// LSTM step: 128x128 tile, 256 thr (8 warps, warp tile 64x32), BK=64,
// 3-buffer depth-2 cp.async pipeline, 2 CTAs/SM, PDL, length-sorted batch.
#define BM_     128
#define BN_     128
#define NKT_    10            // 640 / 64
#define STAGE_  32768         // A 16K | W 16K
#define OFF_W_  16384
#define SMEM_DYN_ 99328       // 1K align + 3*32K stages (C 128x132 overlays)

// ---------------------------------------------------------------------------
// Device scratch (static; no allocations allowed)
// ---------------------------------------------------------------------------
__device__ __align__(256) __half g_Xf[NSTEP_ * XSTEP_];      // emb slice (sorted rows)
__device__ __align__(256) __half g_Wf[2][NCOL_ * KC_];       // [dir][n'][k]
__device__ __align__(256) float  g_bias[2][NCOL_];
__device__ __align__(256) __half g_hf[2][BH_];               // ping-pong hidden (sorted)
__device__ __align__(256) float  g_c[BH_];                   // cell state (sorted)
__device__ __align__(256) __half g_hsf[S_ * BH_];            // decoder hiddens (sorted)
__device__ __align__(256) __half g_WoVf[V_TGT_ * H_];        // [v][k]
__device__ int g_perm[B_];       // sorted pos -> original batch row
__device__ int g_len_s[B_];      // lengths in sorted (descending) order
__device__ int g_hist[40];
__device__ int g_cursor[40];

// ---------------------------------------------------------------------------
__device__ __forceinline__ uint32_t smem_u32(const void* p) {
    uint32_t a;
    asm("{ .reg .u64 t; cvta.to.shared.u64 t, %1; cvt.u32.u64 %0, t; }" : "=r"(a) : "l"(p));
    return a;
}
__device__ __forceinline__ void cp16(uint32_t dst, const void* src) {
    asm volatile("cp.async.cg.shared.global [%0], [%1], 16;" :: "r"(dst), "l"(src));
}
__device__ __forceinline__ void ldm_x4(uint32_t* r, uint32_t addr) {
    asm volatile("ldmatrix.sync.aligned.m8n8.x4.shared.b16 {%0,%1,%2,%3}, [%4];"
        : "=r"(r[0]), "=r"(r[1]), "=r"(r[2]), "=r"(r[3]) : "r"(addr));
}
__device__ __forceinline__ void mma16816(float* c, const uint32_t* a, uint32_t b0, uint32_t b1) {
    asm volatile("mma.sync.aligned.m16n8k16.row.col.f32.f16.f16.f32 "
        "{%0,%1,%2,%3}, {%4,%5,%6,%7}, {%8,%9}, {%0,%1,%2,%3};"
        : "+f"(c[0]), "+f"(c[1]), "+f"(c[2]), "+f"(c[3])
        : "r"(a[0]), "r"(a[1]), "r"(a[2]), "r"(a[3]), "r"(b0), "r"(b1));
}
__device__ __forceinline__ float fsig(float x)  { return __fdividef(1.0f, 1.0f + __expf(-x)); }
__device__ __forceinline__ float ftanh(float x) { return 1.0f - __fdividef(2.0f, __expf(2.0f * x) + 1.0f); }

#define PIPE_WAIT2(s, NITER) do { \
    if ((s) < (NITER) - 1) asm volatile("cp.async.wait_group 1;" ::: "memory"); \
    else                   asm volatile("cp.async.wait_group 0;" ::: "memory"); \
} while (0)

// ---------------------------------------------------------------------------
// Counting sort by descending src_len (stable placement not required: each
// row's arithmetic is position-independent, so outputs are value-identical).
// ---------------------------------------------------------------------------
__global__ void sort_init() {
    int i = threadIdx.x;
    if (i < 40) { g_hist[i] = 0; g_cursor[i] = 0; }
}
__global__ void sort_hist(const int* __restrict__ src_len) {
    int m = blockIdx.x * blockDim.x + threadIdx.x;
    if (m < B_) atomicAdd(&g_hist[src_len[m]], 1);
}
__global__ void sort_scan() {
    if (threadIdx.x == 0) {
        int base = 0;
        for (int L = 32; L >= 1; L--) { g_cursor[L] = base; base += g_hist[L]; }
    }
}
__global__ void sort_scatter(const int* __restrict__ src_len) {
    int m = blockIdx.x * blockDim.x + threadIdx.x;
    if (m < B_) {
        int L = src_len[m];
        int pos = atomicAdd(&g_cursor[L], 1);
        g_perm[pos] = m;
        g_len_s[pos] = L;
    }
}

// ---------------------------------------------------------------------------
// Prep: fp16 weights, fp16 embedding slices for all 64 steps (SORTED row
// order via g_perm), summed biases, fp16 WoutT, zeroed state.
// ---------------------------------------------------------------------------
__global__ void prep_kernel(const int* __restrict__ src_seq, const int* __restrict__ tgt_seq,
                            const float* __restrict__ emb_src, const float* __restrict__ emb_tgt,
                            const float* __restrict__ eWih, const float* __restrict__ eWhh,
                            const float* __restrict__ eBih, const float* __restrict__ eBhh,
                            const float* __restrict__ dWih, const float* __restrict__ dWhh,
                            const float* __restrict__ dBih, const float* __restrict__ dBhh,
                            const float* __restrict__ Wout)
{
    const long long t0 = (long long)blockIdx.x * blockDim.x + threadIdx.x;
    const long long st = (long long)gridDim.x * blockDim.x;

    for (long long i = t0; i < (long long)NSTEP_ * XSTEP_; i += st) {
        int k = (int)(i & 127);
        long long sm = i >> 7;
        int m = (int)(sm & (B_ - 1));            // sorted row
        int s = (int)(sm >> 12);
        int mo = g_perm[m];                      // original batch row
        int tok; const float* emb;
        if (s < 32)       { tok = src_seq[mo * S_ + s]; emb = emb_src; }
        else if (s == 32) { tok = SOS_;                 emb = emb_tgt; }
        else              { tok = tgt_seq[mo * S_ + (s - 33)]; emb = emb_tgt; }
        g_Xf[i] = __float2half_rn(emb[tok * E_ + k]);
    }
    for (long long i = t0; i < (long long)NCOL_ * KC_; i += st) {
        int np = (int)(i / KC_);
        int k  = (int)(i - (long long)np * KC_);
        int g = np & 3, n = np >> 2;
        int r = g * H_ + n;                       // PyTorch [i,f,g,o] gate layout
        float ve = (k < E_) ? eWih[r * E_ + k] : eWhh[r * H_ + (k - E_)];
        float vd = (k < E_) ? dWih[r * E_ + k] : dWhh[r * H_ + (k - E_)];
        g_Wf[0][i] = __float2half_rn(ve);
        g_Wf[1][i] = __float2half_rn(vd);
    }
    for (long long i = t0; i < NCOL_; i += st) {
        int g = (int)i & 3, n = (int)i >> 2;
        int r = g * H_ + n;
        g_bias[0][i] = eBih[r] + eBhh[r];
        g_bias[1][i] = dBih[r] + dBhh[r];
    }
    for (long long i = t0; i < (long long)V_TGT_ * H_; i += st)
        g_WoVf[i] = __float2half_rn(Wout[i]);    // Wout is [V][H] = [n][k]
    __half z = __float2half_rn(0.0f);
    for (long long i = t0; i < BH_; i += st) {
        g_hf[0][i] = z;
        g_c[i] = 0.0f;
    }
}

// ---------------------------------------------------------------------------
// Stage loader: kt in [0,10), buffer = kt % 3. A 16KB + W 16KB, SW128 rows.
// kt 0,1 read ONLY X and W (h-independent) -> safe before griddepcontrol.wait.
// ---------------------------------------------------------------------------
__device__ __forceinline__ void load_tile(uint32_t base, int kt, int m0, int n0p, int tid,
    const __half* __restrict__ Xf, const __half* __restrict__ Hf,
    const __half* __restrict__ Wf)
{
    const int kofs = kt * 64;
    uint32_t sb = base + (uint32_t)(kt % 3) * STAGE_;
    #pragma unroll
    for (int i = 0; i < 4; i++) {                 // A: 128 rows x 8 chunks(16B)
        int idx = tid + i * 256;
        int row = idx >> 3, c = idx & 7;
        uint32_t doff = (uint32_t)(row * 128 + ((c * 16) ^ ((row & 7) << 4)));
        const __half* src = (kt < 2)
            ? Xf + (size_t)(m0 + row) * E_ + kofs + c * 8
            : Hf + (size_t)(m0 + row) * H_ + (kofs - E_) + c * 8;
        cp16(sb + doff, src);
    }
    #pragma unroll
    for (int i = 0; i < 4; i++) {                 // W: 128 rows x 8 chunks
        int idx = tid + i * 256;
        int row = idx >> 3, c = idx & 7;
        uint32_t doff = (uint32_t)(row * 128 + ((c * 16) ^ ((row & 7) << 4)));
        cp16(sb + OFF_W_ + doff, Wf + (size_t)(n0p + row) * KC_ + kofs + c * 8);
    }
    asm volatile("cp.async.commit_group;" ::: "memory");
}

// ---------------------------------------------------------------------------
// Fused LSTM step: fp16 mma, fp32 accum; PDL + sorted-batch early exit.
// ---------------------------------------------------------------------------
__global__ __launch_bounds__(256, 2)
void lstm_step(int ss, int dir, int par)
{
    extern __shared__ char dyn_smem[];
    __shared__ __align__(16) float bias_s[BN_];

    // Signal dependent (next step): it may begin its h-independent prologue.
    asm volatile("griddepcontrol.launch_dependents;");

    const int tid  = threadIdx.x;
    const int m0  = blockIdx.x * BM_;
    const int n0p = blockIdx.y * BN_;
    const int hq0 = n0p >> 2;

    const __half* hf_s = g_hf[par];
    __half*       hf_d = g_hf[par ^ 1];

    // -------- block-level early exit: whole 128-row block frozen -----------
    // (g_len_s is sorted DESCENDING, so row m0 holds the block max; it is
    //  prep-written and h-independent -> safe to read before the wait.)
    if (dir == 0 && g_len_s[m0] <= ss) {
        asm volatile("griddepcontrol.wait;");
        // copy this CTA's h slice: 128 rows x 32 h-units = 512 uint4
        #pragma unroll
        for (int i = 0; i < 2; i++) {
            int c4  = i * 256 + tid;
            int m_l = c4 >> 2, ch = c4 & 3;
            size_t idx = (size_t)(m0 + m_l) * H_ + hq0 + ch * 8;
            *(uint4*)(hf_d + idx) = *(const uint4*)(hf_s + idx);
        }
        return;
    }

    const int lane = tid & 31;
    const int wid  = tid >> 5;
    const int warp_m = wid & 1;          // 64-row half
    const int warp_n = wid >> 1;         // 0..3 -> 32-col slice

    uint32_t base = (smem_u32(dyn_smem) + 1023u) & ~1023u;

    const __half* Xf = g_Xf + (size_t)ss * XSTEP_;
    const __half* Wf = g_Wf[dir];

    if (tid < BN_) bias_s[tid] = g_bias[dir][n0p + tid];

    float acc[4][4][4];
    #pragma unroll
    for (int mt = 0; mt < 4; mt++)
        #pragma unroll
        for (int nt = 0; nt < 4; nt++)
            #pragma unroll
            for (int q = 0; q < 4; q++) acc[mt][nt][q] = 0.0f;

    uint32_t aRow[4], aXor[4];
    #pragma unroll
    for (int mt = 0; mt < 4; mt++) {
        int row = warp_m * 64 + mt * 16 + (lane & 15);
        aRow[mt] = (uint32_t)(row * 128 + ((lane >> 4) * 16));
        aXor[mt] = (uint32_t)((row & 7) << 4);
    }
    uint32_t bRow[2], bXor[2];
    #pragma unroll
    for (int bt = 0; bt < 2; bt++) {
        int row = warp_n * 32 + bt * 16 + ((lane >> 4) & 1) * 8 + (lane & 7);
        bRow[bt] = (uint32_t)(row * 128 + (((lane >> 3) & 1) * 16));
        bXor[bt] = (uint32_t)((row & 7) << 4);
    }

    // h-independent prologue: overlaps predecessor's tail under PDL.
    load_tile(base, 0, m0, n0p, tid, Xf, hf_s, Wf);
    load_tile(base, 1, m0, n0p, tid, Xf, hf_s, Wf);

    // Predecessor grid must fully complete before touching h / c.
    asm volatile("griddepcontrol.wait;");

    for (int s = 0; s < NKT_; s++) {
        PIPE_WAIT2(s, NKT_);
        __syncthreads();
        if (s + 2 < NKT_)
            load_tile(base, s + 2, m0, n0p, tid, Xf, hf_s, Wf);

        const uint32_t Ab = base + (uint32_t)(s % 3) * STAGE_;
        const uint32_t Wb = Ab + OFF_W_;

        #pragma unroll
        for (int k16 = 0; k16 < 4; k16++) {
            uint32_t kb = (uint32_t)(k16 * 32);
            uint32_t a[4][4], w[2][4];
            #pragma unroll
            for (int mt = 0; mt < 4; mt++)
                ldm_x4(a[mt], Ab + ((aRow[mt] + kb) ^ aXor[mt]));
            #pragma unroll
            for (int bt = 0; bt < 2; bt++)
                ldm_x4(w[bt], Wb + ((bRow[bt] + kb) ^ bXor[bt]));
            #pragma unroll
            for (int mt = 0; mt < 4; mt++)
                #pragma unroll
                for (int nt = 0; nt < 4; nt++) {
                    int bt = nt >> 1, q = nt & 1;
                    mma16816(acc[mt][nt], a[mt], w[bt][2 * q], w[bt][2 * q + 1]);
                }
        }
    }
    __syncthreads();   // drain stage-buffer reads before C overlay

    // ------------------ epilogue: C -> smem (stage area drained) -------------
    float* Cs;
    {
        uintptr_t g = (uintptr_t)dyn_smem;
        uintptr_t delta = (uintptr_t)(base - smem_u32(dyn_smem));
        Cs = (float*)(g + delta);
    }
    const int CSTRIDE = 132;

    #pragma unroll
    for (int mt = 0; mt < 4; mt++)
        #pragma unroll
        for (int nt = 0; nt < 4; nt++) {
            int r   = warp_m * 64 + mt * 16 + (lane >> 2);
            int col = warp_n * 32 + nt * 8 + 2 * (lane & 3);
            Cs[r * CSTRIDE + col]           = acc[mt][nt][0];
            Cs[r * CSTRIDE + col + 1]       = acc[mt][nt][1];
            Cs[(r + 8) * CSTRIDE + col]     = acc[mt][nt][2];
            Cs[(r + 8) * CSTRIDE + col + 1] = acc[mt][nt][3];
        }
    __syncthreads();

    // 128 rows x 32 h-units = 4096 cells, 16 per thread
    #pragma unroll
    for (int i = 0; i < 16; i++) {
        int cell = i * 256 + tid;
        int m_l = cell >> 5;
        int h_l = cell & 31;
        int m = m0 + m_l;
        size_t idx = (size_t)m * H_ + hq0 + h_l;
        bool frozen = (dir == 0) && (ss >= g_len_s[m]);
        if (frozen) {
            hf_d[idx] = hf_s[idx];
        } else {
            const float* gp = &Cs[m_l * CSTRIDE + h_l * 4];
            float gi = gp[0] + bias_s[h_l * 4 + 0];
            float gf = gp[1] + bias_s[h_l * 4 + 1];
            float gg = gp[2] + bias_s[h_l * 4 + 2];
            float go = gp[3] + bias_s[h_l * 4 + 3];
            float cc = fsig(gf) * g_c[idx] + fsig(gi) * ftanh(gg);
            float hv = fsig(go) * ftanh(cc);
            g_c[idx] = cc;
            __half hh = __float2half_rn(hv);
            hf_d[idx] = hh;
            if (dir) g_hsf[(size_t)(ss - 32) * BH_ + idx] = hh;
        }
    }
}

// ---------------------------------------------------------------------------
// Logits: (131072, 512) @ (512, 128) + b_out; sorted rows -> original batch
// rows via g_perm in the epilogue.
// ---------------------------------------------------------------------------
#define LNKT_ 8   // 512 / 64

__device__ __forceinline__ void load_tile_lg(uint32_t base, int kt, int m0, int tid)
{
    const int kofs = kt * 64;
    uint32_t sb = base + (uint32_t)(kt % 3) * STAGE_;
    #pragma unroll
    for (int i = 0; i < 4; i++) {
        int idx = tid + i * 256;
        int row = idx >> 3, c = idx & 7;
        uint32_t doff = (uint32_t)(row * 128 + ((c * 16) ^ ((row & 7) << 4)));
        cp16(sb + doff, g_hsf + (size_t)(m0 + row) * H_ + kofs + c * 8);
    }
    #pragma unroll
    for (int i = 0; i < 4; i++) {
        int idx = tid + i * 256;
        int row = idx >> 3, c = idx & 7;
        uint32_t doff = (uint32_t)(row * 128 + ((c * 16) ^ ((row & 7) << 4)));
        cp16(sb + OFF_W_ + doff, g_WoVf + (size_t)row * H_ + kofs + c * 8);
    }
    asm volatile("cp.async.commit_group;" ::: "memory");
}

__global__ __launch_bounds__(256, 2)
void logits_kernel(const float* __restrict__ b_out, float* __restrict__ out)
{
    extern __shared__ char dyn_smem[];
    __shared__ int perm_s[128];

    const int tid  = threadIdx.x;
    const int lane = tid & 31;
    const int wid  = tid >> 5;
    const int warp_m = wid & 1;
    const int warp_n = wid >> 1;
    const int m0 = blockIdx.x * 128;

    if (tid < 128) perm_s[tid] = g_perm[(m0 & (B_ - 1)) + tid];

    uint32_t base = (smem_u32(dyn_smem) + 1023u) & ~1023u;

    float acc[4][4][4];
    #pragma unroll
    for (int mt = 0; mt < 4; mt++)
        #pragma unroll
        for (int nt = 0; nt < 4; nt++)
            #pragma unroll
            for (int q = 0; q < 4; q++) acc[mt][nt][q] = 0.0f;

    uint32_t aRow[4], aXor[4];
    #pragma unroll
    for (int mt = 0; mt < 4; mt++) {
        int row = warp_m * 64 + mt * 16 + (lane & 15);
        aRow[mt] = (uint32_t)(row * 128 + ((lane >> 4) * 16));
        aXor[mt] = (uint32_t)((row & 7) << 4);
    }
    uint32_t bRow[2], bXor[2];
    #pragma unroll
    for (int bt = 0; bt < 2; bt++) {
        int row = warp_n * 32 + bt * 16 + ((lane >> 4) & 1) * 8 + (lane & 7);
        bRow[bt] = (uint32_t)(row * 128 + (((lane >> 3) & 1) * 16));
        bXor[bt] = (uint32_t)((row & 7) << 4);
    }

    load_tile_lg(base, 0, m0, tid);
    load_tile_lg(base, 1, m0, tid);

    for (int s = 0; s < LNKT_; s++) {
        PIPE_WAIT2(s, LNKT_);
        __syncthreads();
        if (s + 2 < LNKT_) load_tile_lg(base, s + 2, m0, tid);

        const uint32_t Ab = base + (uint32_t)(s % 3) * STAGE_;
        const uint32_t Wb = Ab + OFF_W_;

        #pragma unroll
        for (int k16 = 0; k16 < 4; k16++) {
            uint32_t kb = (uint32_t)(k16 * 32);
            uint32_t a[4][4], w[2][4];
            #pragma unroll
            for (int mt = 0; mt < 4; mt++)
                ldm_x4(a[mt], Ab + ((aRow[mt] + kb) ^ aXor[mt]));
            #pragma unroll
            for (int bt = 0; bt < 2; bt++)
                ldm_x4(w[bt], Wb + ((bRow[bt] + kb) ^ bXor[bt]));
            #pragma unroll
            for (int mt = 0; mt < 4; mt++)
                #pragma unroll
                for (int nt = 0; nt < 4; nt++) {
                    int bt = nt >> 1, q = nt & 1;
                    mma16816(acc[mt][nt], a[mt], w[bt][2 * q], w[bt][2 * q + 1]);
                }
        }
    }
    __syncthreads();   // drain stage-buffer reads before C overlay

    float* Cs;
    {
        uintptr_t g = (uintptr_t)dyn_smem;
        uintptr_t delta = (uintptr_t)(base - smem_u32(dyn_smem));
        Cs = (float*)(g + delta);
    }
    const int CSTRIDE = 132;
    #pragma unroll
    for (int mt = 0; mt < 4; mt++)
        #pragma unroll
        for (int nt = 0; nt < 4; nt++) {
            int r   = warp_m * 64 + mt * 16 + (lane >> 2);
            int col = warp_n * 32 + nt * 8 + 2 * (lane & 3);
            Cs[r * CSTRIDE + col]           = acc[mt][nt][0];
            Cs[r * CSTRIDE + col + 1]       = acc[mt][nt][1];
            Cs[(r + 8) * CSTRIDE + col]     = acc[mt][nt][2];
            Cs[(r + 8) * CSTRIDE + col + 1] = acc[mt][nt][3];
        }
    __syncthreads();

    #pragma unroll
    for (int i = 0; i < 64; i++) {
        int cell = i * 256 + tid;
        int r = cell >> 7;
        int v = cell & 127;
        int m_g = m0 + r;                 // sorted row index within [t*4096, ...)
        int b  = perm_s[r];               // original batch row
        int tt = m_g >> 12;
        out[((size_t)b * S_ + tt) * V_TGT_ + v] = Cs[r * CSTRIDE + v] + b_out[v];
    }
}

// ---------------------------------------------------------------------------
extern "C" void kernel_launch(void* const* d_in, const int* in_sizes, int n_in,
                              void* d_out, int out_size)
{
    (void)in_sizes; (void)n_in; (void)out_size;
    const int*   src_seq = (const int*)  d_in[0];
    const int*   src_len = (const int*)  d_in[1];
    const int*   tgt_seq = (const int*)  d_in[2];
    const float* emb_src = (const float*)d_in[3];
    const float* eWih    = (const float*)d_in[4];
    const float* eWhh    = (const float*)d_in[5];
    const float* eBih    = (const float*)d_in[6];
    const float* eBhh    = (const float*)d_in[7];
    const float* emb_tgt = (const float*)d_in[8];
    const float* dWih    = (const float*)d_in[9];
    const float* dWhh    = (const float*)d_in[10];
    const float* dBih    = (const float*)d_in[11];
    const float* dBhh    = (const float*)d_in[12];
    const float* Wout    = (const float*)d_in[13];
    const float* bout    = (const float*)d_in[14];
    float*       out     = (float*)d_out;

    cudaFuncSetAttribute(lstm_step, cudaFuncAttributeMaxDynamicSharedMemorySize, SMEM_DYN_);
    cudaFuncSetAttribute(logits_kernel, cudaFuncAttributeMaxDynamicSharedMemorySize, SMEM_DYN_);

    // length sort (descending) then prep
    sort_init<<<1, 64>>>();
    sort_hist<<<B_ / 256, 256>>>(src_len);
    sort_scan<<<1, 32>>>();
    sort_scatter<<<B_ / 256, 256>>>(src_len);
    prep_kernel<<<4096, 256>>>(src_seq, tgt_seq, emb_src, emb_tgt,
                               eWih, eWhh, eBih, eBhh,
                               dWih, dWhh, dBih, dBhh, Wout);

    dim3 grid(B_ / BM_, NCOL_ / BN_);   // (32, 16) = 512 CTAs

    // step 0: normal launch (serializes after prep)
    lstm_step<<<grid, 256, SMEM_DYN_>>>(0, 0, 0);

    // steps 1..63: PDL
    for (int s = 1; s < 64; s++) {
        int dir = (s < 32) ? 0 : 1;
        cudaLaunchConfig_t cfg = {};
        cfg.gridDim = grid;
        cfg.blockDim = dim3(256, 1, 1);
        cfg.dynamicSmemBytes = SMEM_DYN_;
        cfg.stream = 0;
        cudaLaunchAttribute attr[1];
        attr[0].id = cudaLaunchAttributeProgrammaticStreamSerialization;
        attr[0].val.programmaticStreamSerializationAllowed = 1;
        cfg.attrs = attr;
        cfg.numAttrs = 1;
        cudaLaunchKernelEx(&cfg, lstm_step, s, dir, s & 1);
    }

    logits_kernel<<<(B_ * S_) / 128, 256, SMEM_DYN_>>>(bout, out);
}